// round 9
// baseline (speedup 1.0000x reference)
#include <cuda_runtime.h>
#include <cuda_fp16.h>
#include <cstdint>

#define T_DIM 4096
#define H_DIM 2048
#define I_DIM 2048
#define E_NUM 16

typedef unsigned long long ull;

// ---------------- static scratch (no allocations allowed) ----------------
__device__ int   d_ids[2 * T_DIM];
__device__ float d_wts[2 * T_DIM];
__device__ int   d_counts[E_NUM];
__device__ int   d_offs[E_NUM + 1];
__device__ int   d_tok[2 * T_DIM];
__device__ int   d_slots[2 * T_DIM];

// fp16 preconverted operands: activations split hi/lo, weights hi only
__device__ __half d_xh[(size_t)T_DIM * H_DIM];                // 16 MB
__device__ __half d_xl[(size_t)T_DIM * H_DIM];                // 16 MB
__device__ __half d_wsh[(size_t)E_NUM * 2 * I_DIM * H_DIM];   // 256 MB
__device__ __half d_w2h[(size_t)E_NUM * H_DIM * I_DIM];       // 128 MB
__device__ __half d_hh[(size_t)2 * T_DIM * I_DIM];            // 32 MB
__device__ __half d_hl[(size_t)2 * T_DIM * I_DIM];            // 32 MB
__device__ float  d_y[(size_t)2 * T_DIM * H_DIM];             // 64 MB

// ---------------- GEMM config: BM=128, BN=256, BK=32, 8 warps (2M x 4N) ----------------
#define BK 32
#define STRIDE 40                        // halfs per smem row (conflict-free frags)
#define OFF_AL_H (128 * STRIDE)          // 5120 halfs
#define OFF_B_H  (2 * 128 * STRIDE)      // 10240 halfs
#define STG_HALF (2 * 128 * STRIDE + 256 * STRIDE)   // 20480 halfs
#define STG_BYTES (STG_HALF * 2)         // 40960 B
#define NSTG 3
#define SMEM_BYTES (NSTG * STG_BYTES)    // 122880 B

// mma.sync m16n8k16 fp16 inputs, fp32 accumulate (legacy tensor path on compute_103)
#define MMA16816(d, a, b0, b1)                                              \
    asm volatile(                                                           \
        "mma.sync.aligned.m16n8k16.row.col.f32.f16.f16.f32 "                \
        "{%0,%1,%2,%3}, {%4,%5,%6,%7}, {%8,%9}, {%0,%1,%2,%3};"             \
        : "+f"((d)[0]), "+f"((d)[1]), "+f"((d)[2]), "+f"((d)[3])            \
        : "r"((a)[0]), "r"((a)[1]), "r"((a)[2]), "r"((a)[3]),               \
          "r"(b0), "r"(b1))

__device__ __forceinline__ void cpa16(uint32_t dst, const void* src, int sz) {
    asm volatile("cp.async.cg.shared.global [%0], [%1], 16, %2;"
                 :: "r"(dst), "l"(src), "r"(sz));
}
#define CPA_COMMIT() asm volatile("cp.async.commit_group;" ::: "memory")
#define CPA_WAIT1()  asm volatile("cp.async.wait_group 1;" ::: "memory")
#define CPA_WAIT0()  asm volatile("cp.async.wait_group 0;" ::: "memory")

__device__ __forceinline__ uint32_t smem_u32(const void* p) {
    uint32_t a;
    asm("{ .reg .u64 t; cvta.to.shared.u64 t, %1; cvt.u32.u64 %0, t; }" : "=r"(a) : "l"(p));
    return a;
}

// split fp32 pair -> packed fp16 hi + packed fp16 lo
__device__ __forceinline__ uint32_t pack_hl(float x, float y, uint32_t& lo) {
    __half hx = __float2half_rn(x), hy = __float2half_rn(y);
    __half lx = __float2half_rn(x - __half2float(hx));
    __half ly = __float2half_rn(y - __half2float(hy));
    lo = ((uint32_t)__half_as_ushort(ly) << 16) | (uint32_t)__half_as_ushort(lx);
    return ((uint32_t)__half_as_ushort(hy) << 16) | (uint32_t)__half_as_ushort(hx);
}
__device__ __forceinline__ uint32_t pack_h(float x, float y) {
    __half2 h = __floats2half2_rn(x, y);
    return *(uint32_t*)&h;
}

// ---------------- 0a. convert fp32 -> fp16 hi+lo (x) ----------------
__global__ void convert_hl_kernel(const float4* __restrict__ src,
                                  uint4* __restrict__ hi, uint4* __restrict__ lo) {
    size_t i = (size_t)blockIdx.x * blockDim.x + threadIdx.x;
    float4 v0 = src[2 * i], v1 = src[2 * i + 1];
    uint32_t h0, h1, h2, h3, l0, l1, l2, l3;
    h0 = pack_hl(v0.x, v0.y, l0);
    h1 = pack_hl(v0.z, v0.w, l1);
    h2 = pack_hl(v1.x, v1.y, l2);
    h3 = pack_hl(v1.z, v1.w, l3);
    hi[i] = make_uint4(h0, h1, h2, h3);
    lo[i] = make_uint4(l0, l1, l2, l3);
}

// ---------------- 0b. convert fp32 -> fp16 hi only (weights) ----------------
__global__ void convert_hi_kernel(const float4* __restrict__ src, uint4* __restrict__ hi) {
    size_t i = (size_t)blockIdx.x * blockDim.x + threadIdx.x;
    float4 v0 = src[2 * i], v1 = src[2 * i + 1];
    hi[i] = make_uint4(pack_h(v0.x, v0.y), pack_h(v0.z, v0.w),
                       pack_h(v1.x, v1.y), pack_h(v1.z, v1.w));
}

// ---------------- 1. gating ----------------
__global__ void gate_kernel(const float* __restrict__ x, const float* __restrict__ gw) {
    int t = blockIdx.x;
    int lane = threadIdx.x & 31;
    int w = threadIdx.x >> 5;
    const float* xr = x + (size_t)t * H_DIM;
    const float* g0 = gw + (size_t)(w * 4) * H_DIM;
    float acc0 = 0.f, acc1 = 0.f, acc2 = 0.f, acc3 = 0.f;
    for (int k = lane; k < H_DIM; k += 32) {
        float xv = xr[k];
        acc0 += xv * g0[k];
        acc1 += xv * g0[H_DIM + k];
        acc2 += xv * g0[2 * H_DIM + k];
        acc3 += xv * g0[3 * H_DIM + k];
    }
    __shared__ float sl[16];
    float accs[4] = {acc0, acc1, acc2, acc3};
#pragma unroll
    for (int j = 0; j < 4; j++) {
        float v = accs[j];
#pragma unroll
        for (int o = 16; o; o >>= 1) v += __shfl_xor_sync(0xffffffff, v, o);
        if (lane == 0) sl[w * 4 + j] = v;
    }
    __syncthreads();
    if (threadIdx.x == 0) {
        float mx = sl[0];
#pragma unroll
        for (int i = 1; i < 16; i++) mx = fmaxf(mx, sl[i]);
        float ex[16];
#pragma unroll
        for (int i = 0; i < 16; i++) ex[i] = expf(sl[i] - mx);
        int b0 = 0;
#pragma unroll
        for (int i = 1; i < 16; i++) if (sl[i] > sl[b0]) b0 = i;
        int b1 = -1;
#pragma unroll
        for (int i = 0; i < 16; i++) {
            if (i == b0) continue;
            if (b1 < 0 || sl[i] > sl[b1]) b1 = i;
        }
        float s = ex[b0] + ex[b1];
        d_ids[2 * t] = b0;
        d_ids[2 * t + 1] = b1;
        d_wts[2 * t] = ex[b0] / s;
        d_wts[2 * t + 1] = ex[b1] / s;
    }
}

// ---------------- 2. routing (parallel segmented scans, deterministic) ----------------
__global__ void count_kernel() {
    int e = blockIdx.x;
    int w = threadIdx.x >> 5, lane = threadIdx.x & 31;
    __shared__ int wcnt[8];
    int cnt = 0;
#pragma unroll
    for (int i = 0; i < 16; i++) {
        int t = w * 512 + i * 32 + lane;
        bool p = (d_ids[2 * t] == e) || (d_ids[2 * t + 1] == e);
        cnt += __popc(__ballot_sync(0xffffffff, p));
    }
    if (lane == 0) wcnt[w] = cnt;
    __syncthreads();
    if (threadIdx.x == 0) {
        int s = 0;
#pragma unroll
        for (int i = 0; i < 8; i++) s += wcnt[i];
        d_counts[e] = s;
    }
}

__global__ void offs_kernel() {
    int s = 0;
    for (int e = 0; e < E_NUM; e++) { d_offs[e] = s; s += d_counts[e]; }
    d_offs[E_NUM] = s;
}

__global__ void fill_kernel() {
    int e = blockIdx.x;
    int w = threadIdx.x >> 5, lane = threadIdx.x & 31;
    __shared__ int wcnt[8], woff[8];
    int cnt = 0;
#pragma unroll
    for (int i = 0; i < 16; i++) {
        int t = w * 512 + i * 32 + lane;
        bool p = (d_ids[2 * t] == e) || (d_ids[2 * t + 1] == e);
        cnt += __popc(__ballot_sync(0xffffffff, p));
    }
    if (lane == 0) wcnt[w] = cnt;
    __syncthreads();
    if (threadIdx.x == 0) {
        int s = 0;
#pragma unroll
        for (int i = 0; i < 8; i++) { woff[i] = s; s += wcnt[i]; }
    }
    __syncthreads();
    int pos = d_offs[e] + woff[w];
#pragma unroll
    for (int i = 0; i < 16; i++) {
        int t = w * 512 + i * 32 + lane;
        int k = (d_ids[2 * t] == e) ? 0 : ((d_ids[2 * t + 1] == e) ? 1 : -1);
        unsigned b = __ballot_sync(0xffffffff, k >= 0);
        if (k >= 0) {
            int idx = pos + __popc(b & ((1u << lane) - 1u));
            d_tok[idx] = t;
            d_slots[2 * t + k] = idx;
        }
        pos += __popc(b);
    }
}

// =========== fragment loads (conflict-free with STRIDE=40) ===========
__device__ __forceinline__ void ld_afrag(uint32_t* f, const __half* p) {
    f[0] = *(const uint32_t*)p;
    f[1] = *(const uint32_t*)(p + 8 * STRIDE);
    f[2] = *(const uint32_t*)(p + 8);
    f[3] = *(const uint32_t*)(p + 8 * STRIDE + 8);
}

// =========== compute core: one BK=32 stage, warp tile 64x64, 2 terms ===========
__device__ __forceinline__ void mma_stage(const __half* cs, int wm, int wn,
                                          int grp, int kq, float acc[4][8][4]) {
#pragma unroll
    for (int ks = 0; ks < 2; ks++) {
        uint32_t ah[4][4], al[4][4];
#pragma unroll
        for (int i = 0; i < 4; i++) {
            const __half* p = cs + (wm * 64 + i * 16 + grp) * STRIDE + ks * 16 + kq;
            ld_afrag(ah[i], p);
            ld_afrag(al[i], p + OFF_AL_H);
        }
#pragma unroll
        for (int j = 0; j < 8; j++) {
            const __half* pb = cs + OFF_B_H + (wn * 64 + j * 8 + grp) * STRIDE + ks * 16 + kq;
            uint32_t b0 = *(const uint32_t*)pb;
            uint32_t b1 = *(const uint32_t*)(pb + 8);
#pragma unroll
            for (int i = 0; i < 4; i++) {
                MMA16816(acc[i][j], ah[i], b0, b1);
                MMA16816(acc[i][j], al[i], b0, b1);
            }
        }
    }
}

// =========== loader: A hi+lo (row tid>>1, half-row tid&1) + B (row tid) ===========
__device__ __forceinline__ void load_stage(uint32_t smbase, int s, int k0,
                                           int arow, int seg,
                                           const __half* aH, const __half* aL,
                                           const __half* bsrc, int predA) {
    uint32_t sb = smbase + (uint32_t)s * STG_BYTES;
    uint32_t da = sb + (uint32_t)(arow * (STRIDE * 2) + seg * 32);
    cpa16(da,                  aH + k0,     predA);
    cpa16(da + 16,             aH + k0 + 8, predA);
    cpa16(da + OFF_AL_H * 2,       aL + k0,     predA);
    cpa16(da + OFF_AL_H * 2 + 16,  aL + k0 + 8, predA);
    uint32_t db = sb + OFF_B_H * 2 + (uint32_t)((arow * 2 + seg) * (STRIDE * 2));
    cpa16(db,      bsrc + k0,      16);
    cpa16(db + 16, bsrc + k0 + 8,  16);
    cpa16(db + 32, bsrc + k0 + 16, 16);
    cpa16(db + 48, bsrc + k0 + 24, 16);
}

// ---------------- 3. GEMM1 + fused SiLU*U -> d_hh/d_hl ----------------
// grid (32, I/128, E). BN=256 B-rows: g=row>>5, icol = n0+(g>>1)*32+(row&31); g&1? up:gate
__global__ void __launch_bounds__(256, 1) gemm1_kernel() {
    int e = blockIdx.z;
    int cnt = d_counts[e];
    int mbase = blockIdx.x * 128;
    if (mbase >= cnt) return;
    int off = d_offs[e];
    int n0 = blockIdx.y * 128;

    extern __shared__ __align__(16) __half sm[];
    uint32_t smbase = smem_u32(sm);

    int tid = threadIdx.x;
    int lane = tid & 31, wid = tid >> 5;
    int wm = wid & 1, wn = wid >> 1;
    int grp = lane >> 2, kq = (lane & 3) * 2;

    int arow = tid >> 1;
    int seg = tid & 1;
    int mrow = mbase + arow;
    int predA = (mrow < cnt) ? 16 : 0;
    size_t atok = predA ? (size_t)d_tok[off + mrow] : 0;
    const __half* aH = d_xh + atok * H_DIM + seg * 16;
    const __half* aL = d_xl + atok * H_DIM + seg * 16;
    int br = tid;
    int g = br >> 5;
    int icol = n0 + (g >> 1) * 32 + (br & 31);
    size_t brow = (size_t)e * (2 * I_DIM) + ((g & 1) ? I_DIM + icol : icol);
    const __half* bsrc = d_wsh + brow * H_DIM;

    float acc[4][8][4];
#pragma unroll
    for (int i = 0; i < 4; i++)
#pragma unroll
        for (int j = 0; j < 8; j++)
#pragma unroll
            for (int r = 0; r < 4; r++) acc[i][j][r] = 0.f;

    const int NIT = H_DIM / BK;
    load_stage(smbase, 0, 0, arow, seg, aH, aL, bsrc, predA);
    CPA_COMMIT();
    load_stage(smbase, 1, BK, arow, seg, aH, aL, bsrc, predA);
    CPA_COMMIT();
    for (int c = 0; c < NIT; c++) {
        if (c == NIT - 1) { CPA_WAIT0(); } else { CPA_WAIT1(); }
        __syncthreads();
        mma_stage(sm + (c % NSTG) * STG_HALF, wm, wn, grp, kq, acc);
        if (c + 2 < NIT) {
            load_stage(smbase, (c + 2) % NSTG, (c + 2) * BK, arow, seg, aH, aL, bsrc, predA);
            CPA_COMMIT();
        }
    }

    // epilogue: silu(g)*u -> fp16 hi/lo
#pragma unroll
    for (int i = 0; i < 4; i++)
#pragma unroll
        for (int rs = 0; rs < 2; rs++) {
            int m = mbase + wm * 64 + i * 16 + grp + rs * 8;
            if (m >= cnt) continue;
            size_t rowp = (size_t)(off + m) * I_DIM;
#pragma unroll
            for (int j = 0; j < 4; j++) {
                int ic = n0 + wn * 32 + j * 8 + kq;
                float g0 = acc[i][j][rs * 2],     g1 = acc[i][j][rs * 2 + 1];
                float u0 = acc[i][j + 4][rs * 2], u1 = acc[i][j + 4][rs * 2 + 1];
                float h0 = u0 * g0 / (1.f + expf(-g0));
                float h1 = u1 * g1 / (1.f + expf(-g1));
                __half hh0 = __float2half_rn(h0);
                __half hh1 = __float2half_rn(h1);
                __half hl0 = __float2half_rn(h0 - __half2float(hh0));
                __half hl1 = __float2half_rn(h1 - __half2float(hh1));
                *(__half2*)(d_hh + rowp + ic) = __halves2half2(hh0, hh1);
                *(__half2*)(d_hl + rowp + ic) = __halves2half2(hl0, hl1);
            }
        }
}

// ---------------- 4. GEMM2: y = h @ W2^T -> d_y ----------------
// grid (32, H/256, E). BM=128, BN=256, BK=32.
__global__ void __launch_bounds__(256, 1) gemm2_kernel() {
    int e = blockIdx.z;
    int cnt = d_counts[e];
    int mbase = blockIdx.x * 128;
    if (mbase >= cnt) return;
    int off = d_offs[e];
    int n0 = blockIdx.y * 256;

    extern __shared__ __align__(16) __half sm[];
    uint32_t smbase = smem_u32(sm);

    int tid = threadIdx.x;
    int lane = tid & 31, wid = tid >> 5;
    int wm = wid & 1, wn = wid >> 1;
    int grp = lane >> 2, kq = (lane & 3) * 2;

    int arow = tid >> 1;
    int seg = tid & 1;
    int mrow = mbase + arow;
    int predA = (mrow < cnt) ? 16 : 0;
    size_t aoff = predA ? (size_t)(off + mrow) : 0;
    const __half* aH = d_hh + aoff * I_DIM + seg * 16;
    const __half* aL = d_hl + aoff * I_DIM + seg * 16;
    const __half* bsrc = d_w2h + ((size_t)e * H_DIM + n0 + tid) * I_DIM;

    float acc[4][8][4];
#pragma unroll
    for (int i = 0; i < 4; i++)
#pragma unroll
        for (int j = 0; j < 8; j++)
#pragma unroll
            for (int r = 0; r < 4; r++) acc[i][j][r] = 0.f;

    const int NIT = I_DIM / BK;
    load_stage(smbase, 0, 0, arow, seg, aH, aL, bsrc, predA);
    CPA_COMMIT();
    load_stage(smbase, 1, BK, arow, seg, aH, aL, bsrc, predA);
    CPA_COMMIT();
    for (int c = 0; c < NIT; c++) {
        if (c == NIT - 1) { CPA_WAIT0(); } else { CPA_WAIT1(); }
        __syncthreads();
        mma_stage(sm + (c % NSTG) * STG_HALF, wm, wn, grp, kq, acc);
        if (c + 2 < NIT) {
            load_stage(smbase, (c + 2) % NSTG, (c + 2) * BK, arow, seg, aH, aL, bsrc, predA);
            CPA_COMMIT();
        }
    }

#pragma unroll
    for (int i = 0; i < 4; i++)
#pragma unroll
        for (int rs = 0; rs < 2; rs++) {
            int m = mbase + wm * 64 + i * 16 + grp + rs * 8;
            if (m >= cnt) continue;
            size_t rowp = (size_t)(off + m) * H_DIM;
#pragma unroll
            for (int j = 0; j < 8; j++) {
                int col = n0 + wn * 64 + j * 8 + kq;
                *(float2*)(d_y + rowp + col) =
                    make_float2(acc[i][j][rs * 2], acc[i][j][rs * 2 + 1]);
            }
        }
}

// ---------------- 5. deterministic combine ----------------
__global__ void combine_kernel(float* __restrict__ out) {
    int idx = blockIdx.x * blockDim.x + threadIdx.x;
    int t = idx >> 11;
    int c = idx & 2047;
    float w0 = d_wts[2 * t], w1 = d_wts[2 * t + 1];
    int s0 = d_slots[2 * t], s1 = d_slots[2 * t + 1];
    out[idx] = w0 * d_y[(size_t)s0 * H_DIM + c] + w1 * d_y[(size_t)s1 * H_DIM + c];
}

// ---------------- launch ----------------
extern "C" void kernel_launch(void* const* d_in, const int* in_sizes, int n_in,
                              void* d_out, int out_size) {
    const float* x    = (const float*)d_in[0];
    const float* gw   = (const float*)d_in[1];
    const float* ws   = (const float*)d_in[2];
    const float* w2s  = (const float*)d_in[3];
    float* out = (float*)d_out;

    cudaFuncSetAttribute(gemm1_kernel, cudaFuncAttributeMaxDynamicSharedMemorySize, SMEM_BYTES);
    cudaFuncSetAttribute(gemm2_kernel, cudaFuncAttributeMaxDynamicSharedMemorySize, SMEM_BYTES);

    __half *xh, *xl, *wsh, *w2h;
    cudaGetSymbolAddress((void**)&xh,  d_xh);
    cudaGetSymbolAddress((void**)&xl,  d_xl);
    cudaGetSymbolAddress((void**)&wsh, d_wsh);
    cudaGetSymbolAddress((void**)&w2h, d_w2h);

    convert_hl_kernel<<<4096, 256>>>((const float4*)x, (uint4*)xh, (uint4*)xl);
    convert_hi_kernel<<<65536, 256>>>((const float4*)ws, (uint4*)wsh);
    convert_hi_kernel<<<32768, 256>>>((const float4*)w2s, (uint4*)w2h);

    gate_kernel<<<T_DIM, 128>>>(x, gw);
    count_kernel<<<E_NUM, 256>>>();
    offs_kernel<<<1, 1>>>();
    fill_kernel<<<E_NUM, 256>>>();

    dim3 g1(32, I_DIM / 128, E_NUM);   // (32, 16, 16)
    gemm1_kernel<<<g1, 256, SMEM_BYTES>>>();

    dim3 g2(32, H_DIM / 256, E_NUM);   // (32, 8, 16)
    gemm2_kernel<<<g2, 256, SMEM_BYTES>>>();

    combine_kernel<<<(T_DIM * H_DIM) / 256, 256>>>(out);
}

// round 10
// speedup vs baseline: 1.6675x; 1.6675x over previous
#include <cuda_runtime.h>
#include <cuda_fp16.h>
#include <cstdint>

#define T_DIM 4096
#define H_DIM 2048
#define I_DIM 2048
#define E_NUM 16

typedef unsigned long long ull;

// ---------------- static scratch (no allocations allowed) ----------------
__device__ int   d_ids[2 * T_DIM];
__device__ float d_wts[2 * T_DIM];
__device__ int   d_counts[E_NUM];
__device__ int   d_offs[E_NUM + 1];
__device__ int   d_tok[2 * T_DIM];
__device__ int   d_slots[2 * T_DIM];

// fp16 preconverted operands: activations split hi/lo, weights hi only
__device__ __half d_xh[(size_t)T_DIM * H_DIM];                // 16 MB
__device__ __half d_xl[(size_t)T_DIM * H_DIM];                // 16 MB
__device__ __half d_wsh[(size_t)E_NUM * 2 * I_DIM * H_DIM];   // 256 MB
__device__ __half d_w2h[(size_t)E_NUM * H_DIM * I_DIM];       // 128 MB
__device__ __half d_hh[(size_t)2 * T_DIM * I_DIM];            // 32 MB
__device__ __half d_hl[(size_t)2 * T_DIM * I_DIM];            // 32 MB
__device__ float  d_y[(size_t)2 * T_DIM * H_DIM];             // 64 MB

// ---------------- GEMM config: BM=128, BN=128, BK=32, 8 warps (4M x 2N) ----------------
#define BK 32
#define STRIDE 40                        // halfs per smem row (conflict-free frags)
#define TILE_H (128 * STRIDE)            // 5120 halfs per 128x32 tile
#define STG_HALF (3 * TILE_H)            // AH + AL + BH = 15360 halfs
#define STG_BYTES (STG_HALF * 2)         // 30720 B
#define NSTG 3
#define SMEM_BYTES (NSTG * STG_BYTES)    // 92160 B (x2 CTAs = 184320 < 228KB)

// mma.sync m16n8k16 fp16 inputs, fp32 accumulate (legacy tensor path on compute_103)
#define MMA16816(d, a, b0, b1)                                              \
    asm volatile(                                                           \
        "mma.sync.aligned.m16n8k16.row.col.f32.f16.f16.f32 "                \
        "{%0,%1,%2,%3}, {%4,%5,%6,%7}, {%8,%9}, {%0,%1,%2,%3};"             \
        : "+f"((d)[0]), "+f"((d)[1]), "+f"((d)[2]), "+f"((d)[3])            \
        : "r"((a)[0]), "r"((a)[1]), "r"((a)[2]), "r"((a)[3]),               \
          "r"(b0), "r"(b1))

__device__ __forceinline__ void cpa16(uint32_t dst, const void* src, int sz) {
    asm volatile("cp.async.cg.shared.global [%0], [%1], 16, %2;"
                 :: "r"(dst), "l"(src), "r"(sz));
}
#define CPA_COMMIT() asm volatile("cp.async.commit_group;" ::: "memory")
#define CPA_WAIT1()  asm volatile("cp.async.wait_group 1;" ::: "memory")
#define CPA_WAIT0()  asm volatile("cp.async.wait_group 0;" ::: "memory")

__device__ __forceinline__ uint32_t smem_u32(const void* p) {
    uint32_t a;
    asm("{ .reg .u64 t; cvta.to.shared.u64 t, %1; cvt.u32.u64 %0, t; }" : "=r"(a) : "l"(p));
    return a;
}

// split fp32 pair -> packed fp16 hi + packed fp16 lo
__device__ __forceinline__ uint32_t pack_hl(float x, float y, uint32_t& lo) {
    __half hx = __float2half_rn(x), hy = __float2half_rn(y);
    __half lx = __float2half_rn(x - __half2float(hx));
    __half ly = __float2half_rn(y - __half2float(hy));
    lo = ((uint32_t)__half_as_ushort(ly) << 16) | (uint32_t)__half_as_ushort(lx);
    return ((uint32_t)__half_as_ushort(hy) << 16) | (uint32_t)__half_as_ushort(hx);
}
__device__ __forceinline__ uint32_t pack_h(float x, float y) {
    __half2 h = __floats2half2_rn(x, y);
    return *(uint32_t*)&h;
}

// ---------------- 0a. convert fp32 -> fp16 hi+lo (x) ----------------
__global__ void convert_hl_kernel(const float4* __restrict__ src,
                                  uint4* __restrict__ hi, uint4* __restrict__ lo) {
    size_t i = (size_t)blockIdx.x * blockDim.x + threadIdx.x;
    float4 v0 = src[2 * i], v1 = src[2 * i + 1];
    uint32_t h0, h1, h2, h3, l0, l1, l2, l3;
    h0 = pack_hl(v0.x, v0.y, l0);
    h1 = pack_hl(v0.z, v0.w, l1);
    h2 = pack_hl(v1.x, v1.y, l2);
    h3 = pack_hl(v1.z, v1.w, l3);
    hi[i] = make_uint4(h0, h1, h2, h3);
    lo[i] = make_uint4(l0, l1, l2, l3);
}

// ---------------- 0b. convert fp32 -> fp16 hi only (weights) ----------------
__global__ void convert_hi_kernel(const float4* __restrict__ src, uint4* __restrict__ hi) {
    size_t i = (size_t)blockIdx.x * blockDim.x + threadIdx.x;
    float4 v0 = src[2 * i], v1 = src[2 * i + 1];
    hi[i] = make_uint4(pack_h(v0.x, v0.y), pack_h(v0.z, v0.w),
                       pack_h(v1.x, v1.y), pack_h(v1.z, v1.w));
}

// ---------------- 1. gating ----------------
__global__ void gate_kernel(const float* __restrict__ x, const float* __restrict__ gw) {
    int t = blockIdx.x;
    int lane = threadIdx.x & 31;
    int w = threadIdx.x >> 5;
    const float* xr = x + (size_t)t * H_DIM;
    const float* g0 = gw + (size_t)(w * 4) * H_DIM;
    float acc0 = 0.f, acc1 = 0.f, acc2 = 0.f, acc3 = 0.f;
    for (int k = lane; k < H_DIM; k += 32) {
        float xv = xr[k];
        acc0 += xv * g0[k];
        acc1 += xv * g0[H_DIM + k];
        acc2 += xv * g0[2 * H_DIM + k];
        acc3 += xv * g0[3 * H_DIM + k];
    }
    __shared__ float sl[16];
    float accs[4] = {acc0, acc1, acc2, acc3};
#pragma unroll
    for (int j = 0; j < 4; j++) {
        float v = accs[j];
#pragma unroll
        for (int o = 16; o; o >>= 1) v += __shfl_xor_sync(0xffffffff, v, o);
        if (lane == 0) sl[w * 4 + j] = v;
    }
    __syncthreads();
    if (threadIdx.x == 0) {
        float mx = sl[0];
#pragma unroll
        for (int i = 1; i < 16; i++) mx = fmaxf(mx, sl[i]);
        float ex[16];
#pragma unroll
        for (int i = 0; i < 16; i++) ex[i] = expf(sl[i] - mx);
        int b0 = 0;
#pragma unroll
        for (int i = 1; i < 16; i++) if (sl[i] > sl[b0]) b0 = i;
        int b1 = -1;
#pragma unroll
        for (int i = 0; i < 16; i++) {
            if (i == b0) continue;
            if (b1 < 0 || sl[i] > sl[b1]) b1 = i;
        }
        float s = ex[b0] + ex[b1];
        d_ids[2 * t] = b0;
        d_ids[2 * t + 1] = b1;
        d_wts[2 * t] = ex[b0] / s;
        d_wts[2 * t + 1] = ex[b1] / s;
    }
}

// ---------------- 2. routing (parallel segmented scans, deterministic) ----------------
__global__ void count_kernel() {
    int e = blockIdx.x;
    int w = threadIdx.x >> 5, lane = threadIdx.x & 31;
    __shared__ int wcnt[8];
    int cnt = 0;
#pragma unroll
    for (int i = 0; i < 16; i++) {
        int t = w * 512 + i * 32 + lane;
        bool p = (d_ids[2 * t] == e) || (d_ids[2 * t + 1] == e);
        cnt += __popc(__ballot_sync(0xffffffff, p));
    }
    if (lane == 0) wcnt[w] = cnt;
    __syncthreads();
    if (threadIdx.x == 0) {
        int s = 0;
#pragma unroll
        for (int i = 0; i < 8; i++) s += wcnt[i];
        d_counts[e] = s;
    }
}

__global__ void offs_kernel() {
    int s = 0;
    for (int e = 0; e < E_NUM; e++) { d_offs[e] = s; s += d_counts[e]; }
    d_offs[E_NUM] = s;
}

__global__ void fill_kernel() {
    int e = blockIdx.x;
    int w = threadIdx.x >> 5, lane = threadIdx.x & 31;
    __shared__ int wcnt[8], woff[8];
    int cnt = 0;
#pragma unroll
    for (int i = 0; i < 16; i++) {
        int t = w * 512 + i * 32 + lane;
        bool p = (d_ids[2 * t] == e) || (d_ids[2 * t + 1] == e);
        cnt += __popc(__ballot_sync(0xffffffff, p));
    }
    if (lane == 0) wcnt[w] = cnt;
    __syncthreads();
    if (threadIdx.x == 0) {
        int s = 0;
#pragma unroll
        for (int i = 0; i < 8; i++) { woff[i] = s; s += wcnt[i]; }
    }
    __syncthreads();
    int pos = d_offs[e] + woff[w];
#pragma unroll
    for (int i = 0; i < 16; i++) {
        int t = w * 512 + i * 32 + lane;
        int k = (d_ids[2 * t] == e) ? 0 : ((d_ids[2 * t + 1] == e) ? 1 : -1);
        unsigned b = __ballot_sync(0xffffffff, k >= 0);
        if (k >= 0) {
            int idx = pos + __popc(b & ((1u << lane) - 1u));
            d_tok[idx] = t;
            d_slots[2 * t + k] = idx;
        }
        pos += __popc(b);
    }
}

// =========== fragment loads (conflict-free with STRIDE=40) ===========
__device__ __forceinline__ void ld_afrag(uint32_t* f, const __half* p) {
    f[0] = *(const uint32_t*)p;
    f[1] = *(const uint32_t*)(p + 8 * STRIDE);
    f[2] = *(const uint32_t*)(p + 8);
    f[3] = *(const uint32_t*)(p + 8 * STRIDE + 8);
}

// =========== compute core: one BK=32 stage, warp tile 32x64, 2 terms ===========
__device__ __forceinline__ void mma_stage(const __half* cs, int wm, int wn,
                                          int grp, int kq, float acc[2][8][4]) {
#pragma unroll
    for (int ks = 0; ks < 2; ks++) {
        uint32_t ah[2][4], al[2][4];
#pragma unroll
        for (int i = 0; i < 2; i++) {
            const __half* p = cs + (wm * 32 + i * 16 + grp) * STRIDE + ks * 16 + kq;
            ld_afrag(ah[i], p);
            ld_afrag(al[i], p + TILE_H);
        }
#pragma unroll
        for (int j = 0; j < 8; j++) {
            const __half* pb = cs + 2 * TILE_H + (wn * 64 + j * 8 + grp) * STRIDE + ks * 16 + kq;
            uint32_t b0 = *(const uint32_t*)pb;
            uint32_t b1 = *(const uint32_t*)(pb + 8);
#pragma unroll
            for (int i = 0; i < 2; i++) {
                MMA16816(acc[i][j], ah[i], b0, b1);
                MMA16816(acc[i][j], al[i], b0, b1);
            }
        }
    }
}

// =========== loader: 6x cp.async 16B per thread (A hi, A lo, B hi) ===========
__device__ __forceinline__ void load_stage(uint32_t smbase, int s, int k0,
                                           int arow, int seg,
                                           const __half* aH, const __half* aL,
                                           const __half* bH, int predA) {
    uint32_t sb = smbase + (uint32_t)s * STG_BYTES;
    uint32_t da = sb + (uint32_t)(arow * (STRIDE * 2) + seg * 32);
    cpa16(da,                  aH + k0,     predA);
    cpa16(da + 16,             aH + k0 + 8, predA);
    cpa16(da + TILE_H * 2,       aL + k0,     predA);
    cpa16(da + TILE_H * 2 + 16,  aL + k0 + 8, predA);
    cpa16(da + 2 * TILE_H * 2,      bH + k0,     16);
    cpa16(da + 2 * TILE_H * 2 + 16, bH + k0 + 8, 16);
}

// ---------------- 3. GEMM1 + fused SiLU*U -> d_hh/d_hl ----------------
// grid (32, I/64, E). B rows grouped: g=row>>5, icol = n0+(g>>1)*32+(row&31); g&1? up:gate
__global__ void __launch_bounds__(256, 2) gemm1_kernel() {
    int e = blockIdx.z;
    int cnt = d_counts[e];
    int mbase = blockIdx.x * 128;
    if (mbase >= cnt) return;
    int off = d_offs[e];
    int n0 = blockIdx.y * 64;

    extern __shared__ __align__(16) __half sm[];
    uint32_t smbase = smem_u32(sm);

    int tid = threadIdx.x;
    int lane = tid & 31, wid = tid >> 5;
    int wm = wid & 3, wn = wid >> 2;
    int grp = lane >> 2, kq = (lane & 3) * 2;

    int arow = tid >> 1;
    int seg = tid & 1;
    int mrow = mbase + arow;
    int predA = (mrow < cnt) ? 16 : 0;
    size_t atok = predA ? (size_t)d_tok[off + mrow] : 0;
    const __half* aH = d_xh + atok * H_DIM + seg * 16;
    const __half* aL = d_xl + atok * H_DIM + seg * 16;
    int group = arow >> 5, rr = arow & 31;
    int icol = n0 + (group >> 1) * 32 + rr;
    size_t brow = (size_t)e * (2 * I_DIM) + ((group & 1) ? I_DIM + icol : icol);
    const __half* bH = d_wsh + brow * H_DIM + seg * 16;

    float acc[2][8][4];
#pragma unroll
    for (int i = 0; i < 2; i++)
#pragma unroll
        for (int j = 0; j < 8; j++)
#pragma unroll
            for (int r = 0; r < 4; r++) acc[i][j][r] = 0.f;

    const int NIT = H_DIM / BK;
    load_stage(smbase, 0, 0, arow, seg, aH, aL, bH, predA);
    CPA_COMMIT();
    load_stage(smbase, 1, BK, arow, seg, aH, aL, bH, predA);
    CPA_COMMIT();
    for (int c = 0; c < NIT; c++) {
        if (c == NIT - 1) { CPA_WAIT0(); } else { CPA_WAIT1(); }
        __syncthreads();
        mma_stage(sm + (c % NSTG) * STG_HALF, wm, wn, grp, kq, acc);
        if (c + 2 < NIT) {
            load_stage(smbase, (c + 2) % NSTG, (c + 2) * BK, arow, seg, aH, aL, bH, predA);
            CPA_COMMIT();
        }
    }

    // epilogue: silu(g)*u -> fp16 hi/lo  (warp wn: j=gate col, j+4=up col)
#pragma unroll
    for (int i = 0; i < 2; i++)
#pragma unroll
        for (int rs = 0; rs < 2; rs++) {
            int m = mbase + wm * 32 + i * 16 + grp + rs * 8;
            if (m >= cnt) continue;
            size_t rowp = (size_t)(off + m) * I_DIM;
#pragma unroll
            for (int j = 0; j < 4; j++) {
                int ic = n0 + wn * 32 + j * 8 + kq;
                float g0 = acc[i][j][rs * 2],     g1 = acc[i][j][rs * 2 + 1];
                float u0 = acc[i][j + 4][rs * 2], u1 = acc[i][j + 4][rs * 2 + 1];
                float h0 = u0 * g0 / (1.f + expf(-g0));
                float h1 = u1 * g1 / (1.f + expf(-g1));
                __half hh0 = __float2half_rn(h0);
                __half hh1 = __float2half_rn(h1);
                __half hl0 = __float2half_rn(h0 - __half2float(hh0));
                __half hl1 = __float2half_rn(h1 - __half2float(hh1));
                *(__half2*)(d_hh + rowp + ic) = __halves2half2(hh0, hh1);
                *(__half2*)(d_hl + rowp + ic) = __halves2half2(hl0, hl1);
            }
        }
}

// ---------------- 4. GEMM2: y = h @ W2^T -> d_y ----------------
// grid (32, H/128, E). BM=128, BN=128, BK=32.
__global__ void __launch_bounds__(256, 2) gemm2_kernel() {
    int e = blockIdx.z;
    int cnt = d_counts[e];
    int mbase = blockIdx.x * 128;
    if (mbase >= cnt) return;
    int off = d_offs[e];
    int n0 = blockIdx.y * 128;

    extern __shared__ __align__(16) __half sm[];
    uint32_t smbase = smem_u32(sm);

    int tid = threadIdx.x;
    int lane = tid & 31, wid = tid >> 5;
    int wm = wid & 3, wn = wid >> 2;
    int grp = lane >> 2, kq = (lane & 3) * 2;

    int arow = tid >> 1;
    int seg = tid & 1;
    int mrow = mbase + arow;
    int predA = (mrow < cnt) ? 16 : 0;
    size_t aoff = predA ? (size_t)(off + mrow) : 0;
    const __half* aH = d_hh + aoff * I_DIM + seg * 16;
    const __half* aL = d_hl + aoff * I_DIM + seg * 16;
    const __half* bH = d_w2h + ((size_t)e * H_DIM + n0 + arow) * I_DIM + seg * 16;

    float acc[2][8][4];
#pragma unroll
    for (int i = 0; i < 2; i++)
#pragma unroll
        for (int j = 0; j < 8; j++)
#pragma unroll
            for (int r = 0; r < 4; r++) acc[i][j][r] = 0.f;

    const int NIT = I_DIM / BK;
    load_stage(smbase, 0, 0, arow, seg, aH, aL, bH, predA);
    CPA_COMMIT();
    load_stage(smbase, 1, BK, arow, seg, aH, aL, bH, predA);
    CPA_COMMIT();
    for (int c = 0; c < NIT; c++) {
        if (c == NIT - 1) { CPA_WAIT0(); } else { CPA_WAIT1(); }
        __syncthreads();
        mma_stage(sm + (c % NSTG) * STG_HALF, wm, wn, grp, kq, acc);
        if (c + 2 < NIT) {
            load_stage(smbase, (c + 2) % NSTG, (c + 2) * BK, arow, seg, aH, aL, bH, predA);
            CPA_COMMIT();
        }
    }

#pragma unroll
    for (int i = 0; i < 2; i++)
#pragma unroll
        for (int rs = 0; rs < 2; rs++) {
            int m = mbase + wm * 32 + i * 16 + grp + rs * 8;
            if (m >= cnt) continue;
            size_t rowp = (size_t)(off + m) * H_DIM;
#pragma unroll
            for (int j = 0; j < 8; j++) {
                int col = n0 + wn * 64 + j * 8 + kq;
                *(float2*)(d_y + rowp + col) =
                    make_float2(acc[i][j][rs * 2], acc[i][j][rs * 2 + 1]);
            }
        }
}

// ---------------- 5. deterministic combine ----------------
__global__ void combine_kernel(float* __restrict__ out) {
    int idx = blockIdx.x * blockDim.x + threadIdx.x;
    int t = idx >> 11;
    int c = idx & 2047;
    float w0 = d_wts[2 * t], w1 = d_wts[2 * t + 1];
    int s0 = d_slots[2 * t], s1 = d_slots[2 * t + 1];
    out[idx] = w0 * d_y[(size_t)s0 * H_DIM + c] + w1 * d_y[(size_t)s1 * H_DIM + c];
}

// ---------------- launch ----------------
extern "C" void kernel_launch(void* const* d_in, const int* in_sizes, int n_in,
                              void* d_out, int out_size) {
    const float* x    = (const float*)d_in[0];
    const float* gw   = (const float*)d_in[1];
    const float* ws   = (const float*)d_in[2];
    const float* w2s  = (const float*)d_in[3];
    float* out = (float*)d_out;

    cudaFuncSetAttribute(gemm1_kernel, cudaFuncAttributeMaxDynamicSharedMemorySize, SMEM_BYTES);
    cudaFuncSetAttribute(gemm2_kernel, cudaFuncAttributeMaxDynamicSharedMemorySize, SMEM_BYTES);

    __half *xh, *xl, *wsh, *w2h;
    cudaGetSymbolAddress((void**)&xh,  d_xh);
    cudaGetSymbolAddress((void**)&xl,  d_xl);
    cudaGetSymbolAddress((void**)&wsh, d_wsh);
    cudaGetSymbolAddress((void**)&w2h, d_w2h);

    convert_hl_kernel<<<4096, 256>>>((const float4*)x, (uint4*)xh, (uint4*)xl);
    convert_hi_kernel<<<65536, 256>>>((const float4*)ws, (uint4*)wsh);
    convert_hi_kernel<<<32768, 256>>>((const float4*)w2s, (uint4*)w2h);

    gate_kernel<<<T_DIM, 128>>>(x, gw);
    count_kernel<<<E_NUM, 256>>>();
    offs_kernel<<<1, 1>>>();
    fill_kernel<<<E_NUM, 256>>>();

    dim3 g1(32, I_DIM / 64, E_NUM);    // (32, 32, 16)
    gemm1_kernel<<<g1, 256, SMEM_BYTES>>>();

    dim3 g2(32, H_DIM / 128, E_NUM);   // (32, 16, 16)
    gemm2_kernel<<<g2, 256, SMEM_BYTES>>>();

    combine_kernel<<<(T_DIM * H_DIM) / 256, 256>>>(out);
}

// round 11
// speedup vs baseline: 1.8795x; 1.1271x over previous
#include <cuda_runtime.h>
#include <cuda_fp16.h>
#include <cstdint>

#define T_DIM 4096
#define H_DIM 2048
#define I_DIM 2048
#define E_NUM 16

typedef unsigned long long ull;

// ---------------- static scratch (no allocations allowed) ----------------
__device__ int   d_ids[2 * T_DIM];
__device__ float d_wts[2 * T_DIM];
__device__ int   d_counts[E_NUM];
__device__ int   d_offs[E_NUM + 1];
__device__ int   d_tok[2 * T_DIM];
__device__ int   d_slots[2 * T_DIM];

// fp16 preconverted operands: activations split hi/lo, weights hi only
__device__ __half d_xh[(size_t)T_DIM * H_DIM];                // 16 MB
__device__ __half d_xl[(size_t)T_DIM * H_DIM];                // 16 MB
__device__ __half d_wsh[(size_t)E_NUM * 2 * I_DIM * H_DIM];   // 256 MB
__device__ __half d_w2h[(size_t)E_NUM * H_DIM * I_DIM];       // 128 MB
__device__ __half d_hh[(size_t)2 * T_DIM * I_DIM];            // 32 MB
__device__ __half d_hl[(size_t)2 * T_DIM * I_DIM];            // 32 MB
__device__ float  d_y[(size_t)2 * T_DIM * H_DIM];             // 64 MB

// ---------------- GEMM config: BM=128, BN=128, BK=32, 8 warps (4M x 2N) ----------------
#define BK 32
#define STRIDE 40                        // halfs per smem row (conflict-free frags)
#define TILE_H (128 * STRIDE)            // 5120 halfs per 128x32 tile
#define STG_HALF (3 * TILE_H)            // AH + AL + BH = 15360 halfs
#define STG_BYTES (STG_HALF * 2)         // 30720 B
#define NSTG 3
#define SMEM_BYTES (NSTG * STG_BYTES)    // 92160 B (x2 CTAs = 184320 < 228KB)

// mma.sync m16n8k16 fp16 inputs, fp32 accumulate (legacy tensor path on compute_103)
#define MMA16816(d, a, b0, b1)                                              \
    asm volatile(                                                           \
        "mma.sync.aligned.m16n8k16.row.col.f32.f16.f16.f32 "                \
        "{%0,%1,%2,%3}, {%4,%5,%6,%7}, {%8,%9}, {%0,%1,%2,%3};"             \
        : "+f"((d)[0]), "+f"((d)[1]), "+f"((d)[2]), "+f"((d)[3])            \
        : "r"((a)[0]), "r"((a)[1]), "r"((a)[2]), "r"((a)[3]),               \
          "r"(b0), "r"(b1))

// ldmatrix m8n8.x4 (sm_75+, valid on compute_103)
__device__ __forceinline__ void ldsm4(uint32_t* f, uint32_t a) {
    asm volatile("ldmatrix.sync.aligned.m8n8.x4.shared.b16 {%0,%1,%2,%3}, [%4];"
                 : "=r"(f[0]), "=r"(f[1]), "=r"(f[2]), "=r"(f[3]) : "r"(a));
}

__device__ __forceinline__ void cpa16(uint32_t dst, const void* src, int sz) {
    asm volatile("cp.async.cg.shared.global [%0], [%1], 16, %2;"
                 :: "r"(dst), "l"(src), "r"(sz));
}
#define CPA_COMMIT() asm volatile("cp.async.commit_group;" ::: "memory")
#define CPA_WAIT1()  asm volatile("cp.async.wait_group 1;" ::: "memory")
#define CPA_WAIT0()  asm volatile("cp.async.wait_group 0;" ::: "memory")

__device__ __forceinline__ uint32_t smem_u32(const void* p) {
    uint32_t a;
    asm("{ .reg .u64 t; cvta.to.shared.u64 t, %1; cvt.u32.u64 %0, t; }" : "=r"(a) : "l"(p));
    return a;
}

// split fp32 pair -> packed fp16 hi + packed fp16 lo
__device__ __forceinline__ uint32_t pack_hl(float x, float y, uint32_t& lo) {
    __half hx = __float2half_rn(x), hy = __float2half_rn(y);
    __half lx = __float2half_rn(x - __half2float(hx));
    __half ly = __float2half_rn(y - __half2float(hy));
    lo = ((uint32_t)__half_as_ushort(ly) << 16) | (uint32_t)__half_as_ushort(lx);
    return ((uint32_t)__half_as_ushort(hy) << 16) | (uint32_t)__half_as_ushort(hx);
}
__device__ __forceinline__ uint32_t pack_h(float x, float y) {
    __half2 h = __floats2half2_rn(x, y);
    return *(uint32_t*)&h;
}

// ---------------- 0a. convert fp32 -> fp16 hi+lo (x) ----------------
__global__ void convert_hl_kernel(const float4* __restrict__ src,
                                  uint4* __restrict__ hi, uint4* __restrict__ lo) {
    size_t i = (size_t)blockIdx.x * blockDim.x + threadIdx.x;
    float4 v0 = src[2 * i], v1 = src[2 * i + 1];
    uint32_t h0, h1, h2, h3, l0, l1, l2, l3;
    h0 = pack_hl(v0.x, v0.y, l0);
    h1 = pack_hl(v0.z, v0.w, l1);
    h2 = pack_hl(v1.x, v1.y, l2);
    h3 = pack_hl(v1.z, v1.w, l3);
    hi[i] = make_uint4(h0, h1, h2, h3);
    lo[i] = make_uint4(l0, l1, l2, l3);
}

// ---------------- 0b. convert fp32 -> fp16 hi only (weights) ----------------
__global__ void convert_hi_kernel(const float4* __restrict__ src, uint4* __restrict__ hi) {
    size_t i = (size_t)blockIdx.x * blockDim.x + threadIdx.x;
    float4 v0 = src[2 * i], v1 = src[2 * i + 1];
    hi[i] = make_uint4(pack_h(v0.x, v0.y), pack_h(v0.z, v0.w),
                       pack_h(v1.x, v1.y), pack_h(v1.z, v1.w));
}

// ---------------- 1. gating (float4 vectorized) ----------------
__global__ void gate_kernel(const float* __restrict__ x, const float* __restrict__ gw) {
    int t = blockIdx.x;
    int lane = threadIdx.x & 31;
    int w = threadIdx.x >> 5;
    const float* xr = x + (size_t)t * H_DIM;
    const float* g0 = gw + (size_t)(w * 4) * H_DIM;
    float acc0 = 0.f, acc1 = 0.f, acc2 = 0.f, acc3 = 0.f;
    for (int k = lane * 4; k < H_DIM; k += 128) {
        float4 xv = *(const float4*)(xr + k);
        float4 a0 = *(const float4*)(g0 + k);
        float4 a1 = *(const float4*)(g0 + H_DIM + k);
        float4 a2 = *(const float4*)(g0 + 2 * H_DIM + k);
        float4 a3 = *(const float4*)(g0 + 3 * H_DIM + k);
        acc0 += xv.x * a0.x + xv.y * a0.y + xv.z * a0.z + xv.w * a0.w;
        acc1 += xv.x * a1.x + xv.y * a1.y + xv.z * a1.z + xv.w * a1.w;
        acc2 += xv.x * a2.x + xv.y * a2.y + xv.z * a2.z + xv.w * a2.w;
        acc3 += xv.x * a3.x + xv.y * a3.y + xv.z * a3.z + xv.w * a3.w;
    }
    __shared__ float sl[16];
    float accs[4] = {acc0, acc1, acc2, acc3};
#pragma unroll
    for (int j = 0; j < 4; j++) {
        float v = accs[j];
#pragma unroll
        for (int o = 16; o; o >>= 1) v += __shfl_xor_sync(0xffffffff, v, o);
        if (lane == 0) sl[w * 4 + j] = v;
    }
    __syncthreads();
    if (threadIdx.x == 0) {
        float mx = sl[0];
#pragma unroll
        for (int i = 1; i < 16; i++) mx = fmaxf(mx, sl[i]);
        float ex[16];
#pragma unroll
        for (int i = 0; i < 16; i++) ex[i] = expf(sl[i] - mx);
        int b0 = 0;
#pragma unroll
        for (int i = 1; i < 16; i++) if (sl[i] > sl[b0]) b0 = i;
        int b1 = -1;
#pragma unroll
        for (int i = 0; i < 16; i++) {
            if (i == b0) continue;
            if (b1 < 0 || sl[i] > sl[b1]) b1 = i;
        }
        float s = ex[b0] + ex[b1];
        d_ids[2 * t] = b0;
        d_ids[2 * t + 1] = b1;
        d_wts[2 * t] = ex[b0] / s;
        d_wts[2 * t + 1] = ex[b1] / s;
    }
}

// ---------------- 2. routing (parallel segmented scans, deterministic) ----------------
__global__ void count_kernel() {
    int e = blockIdx.x;
    int w = threadIdx.x >> 5, lane = threadIdx.x & 31;
    __shared__ int wcnt[8];
    int cnt = 0;
#pragma unroll
    for (int i = 0; i < 16; i++) {
        int t = w * 512 + i * 32 + lane;
        bool p = (d_ids[2 * t] == e) || (d_ids[2 * t + 1] == e);
        cnt += __popc(__ballot_sync(0xffffffff, p));
    }
    if (lane == 0) wcnt[w] = cnt;
    __syncthreads();
    if (threadIdx.x == 0) {
        int s = 0;
#pragma unroll
        for (int i = 0; i < 8; i++) s += wcnt[i];
        d_counts[e] = s;
    }
}

__global__ void offs_kernel() {
    int s = 0;
    for (int e = 0; e < E_NUM; e++) { d_offs[e] = s; s += d_counts[e]; }
    d_offs[E_NUM] = s;
}

__global__ void fill_kernel() {
    int e = blockIdx.x;
    int w = threadIdx.x >> 5, lane = threadIdx.x & 31;
    __shared__ int wcnt[8], woff[8];
    int cnt = 0;
#pragma unroll
    for (int i = 0; i < 16; i++) {
        int t = w * 512 + i * 32 + lane;
        bool p = (d_ids[2 * t] == e) || (d_ids[2 * t + 1] == e);
        cnt += __popc(__ballot_sync(0xffffffff, p));
    }
    if (lane == 0) wcnt[w] = cnt;
    __syncthreads();
    if (threadIdx.x == 0) {
        int s = 0;
#pragma unroll
        for (int i = 0; i < 8; i++) { woff[i] = s; s += wcnt[i]; }
    }
    __syncthreads();
    int pos = d_offs[e] + woff[w];
#pragma unroll
    for (int i = 0; i < 16; i++) {
        int t = w * 512 + i * 32 + lane;
        int k = (d_ids[2 * t] == e) ? 0 : ((d_ids[2 * t + 1] == e) ? 1 : -1);
        unsigned b = __ballot_sync(0xffffffff, k >= 0);
        if (k >= 0) {
            int idx = pos + __popc(b & ((1u << lane) - 1u));
            d_tok[idx] = t;
            d_slots[2 * t + k] = idx;
        }
        pos += __popc(b);
    }
}

// =========== compute core: one BK=32 stage, warp tile 32x64, 2 terms, ldmatrix ===========
// aoff/boff: per-lane byte offsets (relative to stage base) computed in prologue.
__device__ __forceinline__ void mma_stage(uint32_t sb, uint32_t aoff, uint32_t boff,
                                          float acc[2][8][4]) {
#pragma unroll
    for (int ks = 0; ks < 2; ks++) {
        uint32_t ah[2][4], al[2][4];
#pragma unroll
        for (int i = 0; i < 2; i++) {
            ldsm4(ah[i], sb + aoff + i * (16 * STRIDE * 2) + ks * 32);
            ldsm4(al[i], sb + aoff + TILE_H * 2 + i * (16 * STRIDE * 2) + ks * 32);
        }
#pragma unroll
        for (int jp = 0; jp < 4; jp++) {
            uint32_t bf[4];
            ldsm4(bf, sb + boff + jp * (16 * STRIDE * 2) + ks * 32);
#pragma unroll
            for (int i = 0; i < 2; i++) {
                MMA16816(acc[i][2 * jp],     ah[i], bf[0], bf[1]);
                MMA16816(acc[i][2 * jp],     al[i], bf[0], bf[1]);
                MMA16816(acc[i][2 * jp + 1], ah[i], bf[2], bf[3]);
                MMA16816(acc[i][2 * jp + 1], al[i], bf[2], bf[3]);
            }
        }
    }
}

// =========== loader: 6x cp.async 16B per thread (A hi, A lo, B hi) ===========
__device__ __forceinline__ void load_stage(uint32_t smbase, int s, int k0,
                                           int arow, int seg,
                                           const __half* aH, const __half* aL,
                                           const __half* bH, int predA) {
    uint32_t sb = smbase + (uint32_t)s * STG_BYTES;
    uint32_t da = sb + (uint32_t)(arow * (STRIDE * 2) + seg * 32);
    cpa16(da,                  aH + k0,     predA);
    cpa16(da + 16,             aH + k0 + 8, predA);
    cpa16(da + TILE_H * 2,       aL + k0,     predA);
    cpa16(da + TILE_H * 2 + 16,  aL + k0 + 8, predA);
    cpa16(da + 2 * TILE_H * 2,      bH + k0,     16);
    cpa16(da + 2 * TILE_H * 2 + 16, bH + k0 + 8, 16);
}

// ldmatrix lane-offset helpers (byte offsets relative to stage base)
__device__ __forceinline__ uint32_t mk_aoff(int wm, int lane) {
    int row = wm * 32 + (lane & 7) + ((lane >> 3) & 1) * 8;
    int col8 = ((lane >> 4) & 1) * 8;
    return (uint32_t)((row * STRIDE + col8) * 2);
}
__device__ __forceinline__ uint32_t mk_boff(int wn, int lane) {
    int row = wn * 64 + (lane & 7) + (lane >> 4) * 8;
    int col8 = ((lane >> 3) & 1) * 8;
    return (uint32_t)((2 * TILE_H + row * STRIDE + col8) * 2);
}

// ---------------- 3. GEMM1 + fused SiLU*U -> d_hh/d_hl ----------------
// grid (32, I/64, E). B rows grouped: g=row>>5, icol = n0+(g>>1)*32+(row&31); g&1? up:gate
__global__ void __launch_bounds__(256, 2) gemm1_kernel() {
    int e = blockIdx.z;
    int cnt = d_counts[e];
    int mbase = blockIdx.x * 128;
    if (mbase >= cnt) return;
    int off = d_offs[e];
    int n0 = blockIdx.y * 64;

    extern __shared__ __align__(16) __half sm[];
    uint32_t smbase = smem_u32(sm);

    int tid = threadIdx.x;
    int lane = tid & 31, wid = tid >> 5;
    int wm = wid & 3, wn = wid >> 2;
    int grp = lane >> 2, kq = (lane & 3) * 2;

    int arow = tid >> 1;
    int seg = tid & 1;
    int mrow = mbase + arow;
    int predA = (mrow < cnt) ? 16 : 0;
    size_t atok = predA ? (size_t)d_tok[off + mrow] : 0;
    const __half* aH = d_xh + atok * H_DIM + seg * 16;
    const __half* aL = d_xl + atok * H_DIM + seg * 16;
    int group = arow >> 5, rr = arow & 31;
    int icol = n0 + (group >> 1) * 32 + rr;
    size_t brow = (size_t)e * (2 * I_DIM) + ((group & 1) ? I_DIM + icol : icol);
    const __half* bH = d_wsh + brow * H_DIM + seg * 16;

    uint32_t aoff = mk_aoff(wm, lane), boff = mk_boff(wn, lane);

    float acc[2][8][4];
#pragma unroll
    for (int i = 0; i < 2; i++)
#pragma unroll
        for (int j = 0; j < 8; j++)
#pragma unroll
            for (int r = 0; r < 4; r++) acc[i][j][r] = 0.f;

    const int NIT = H_DIM / BK;
    load_stage(smbase, 0, 0, arow, seg, aH, aL, bH, predA);
    CPA_COMMIT();
    load_stage(smbase, 1, BK, arow, seg, aH, aL, bH, predA);
    CPA_COMMIT();
    for (int c = 0; c < NIT; c++) {
        if (c == NIT - 1) { CPA_WAIT0(); } else { CPA_WAIT1(); }
        __syncthreads();
        mma_stage(smbase + (uint32_t)(c % NSTG) * STG_BYTES, aoff, boff, acc);
        if (c + 2 < NIT) {
            load_stage(smbase, (c + 2) % NSTG, (c + 2) * BK, arow, seg, aH, aL, bH, predA);
            CPA_COMMIT();
        }
    }

    // epilogue: silu(g)*u -> fp16 hi/lo  (warp wn: j=gate col, j+4=up col)
#pragma unroll
    for (int i = 0; i < 2; i++)
#pragma unroll
        for (int rs = 0; rs < 2; rs++) {
            int m = mbase + wm * 32 + i * 16 + grp + rs * 8;
            if (m >= cnt) continue;
            size_t rowp = (size_t)(off + m) * I_DIM;
#pragma unroll
            for (int j = 0; j < 4; j++) {
                int ic = n0 + wn * 32 + j * 8 + kq;
                float g0 = acc[i][j][rs * 2],     g1 = acc[i][j][rs * 2 + 1];
                float u0 = acc[i][j + 4][rs * 2], u1 = acc[i][j + 4][rs * 2 + 1];
                float h0 = u0 * g0 / (1.f + expf(-g0));
                float h1 = u1 * g1 / (1.f + expf(-g1));
                __half hh0 = __float2half_rn(h0);
                __half hh1 = __float2half_rn(h1);
                __half hl0 = __float2half_rn(h0 - __half2float(hh0));
                __half hl1 = __float2half_rn(h1 - __half2float(hh1));
                *(__half2*)(d_hh + rowp + ic) = __halves2half2(hh0, hh1);
                *(__half2*)(d_hl + rowp + ic) = __halves2half2(hl0, hl1);
            }
        }
}

// ---------------- 4. GEMM2: y = h @ W2^T -> d_y ----------------
// grid (32, H/128, E). BM=128, BN=128, BK=32.
__global__ void __launch_bounds__(256, 2) gemm2_kernel() {
    int e = blockIdx.z;
    int cnt = d_counts[e];
    int mbase = blockIdx.x * 128;
    if (mbase >= cnt) return;
    int off = d_offs[e];
    int n0 = blockIdx.y * 128;

    extern __shared__ __align__(16) __half sm[];
    uint32_t smbase = smem_u32(sm);

    int tid = threadIdx.x;
    int lane = tid & 31, wid = tid >> 5;
    int wm = wid & 3, wn = wid >> 2;
    int grp = lane >> 2, kq = (lane & 3) * 2;

    int arow = tid >> 1;
    int seg = tid & 1;
    int mrow = mbase + arow;
    int predA = (mrow < cnt) ? 16 : 0;
    size_t aoff_g = predA ? (size_t)(off + mrow) : 0;
    const __half* aH = d_hh + aoff_g * I_DIM + seg * 16;
    const __half* aL = d_hl + aoff_g * I_DIM + seg * 16;
    const __half* bH = d_w2h + ((size_t)e * H_DIM + n0 + arow) * I_DIM + seg * 16;

    uint32_t aoff = mk_aoff(wm, lane), boff = mk_boff(wn, lane);

    float acc[2][8][4];
#pragma unroll
    for (int i = 0; i < 2; i++)
#pragma unroll
        for (int j = 0; j < 8; j++)
#pragma unroll
            for (int r = 0; r < 4; r++) acc[i][j][r] = 0.f;

    const int NIT = I_DIM / BK;
    load_stage(smbase, 0, 0, arow, seg, aH, aL, bH, predA);
    CPA_COMMIT();
    load_stage(smbase, 1, BK, arow, seg, aH, aL, bH, predA);
    CPA_COMMIT();
    for (int c = 0; c < NIT; c++) {
        if (c == NIT - 1) { CPA_WAIT0(); } else { CPA_WAIT1(); }
        __syncthreads();
        mma_stage(smbase + (uint32_t)(c % NSTG) * STG_BYTES, aoff, boff, acc);
        if (c + 2 < NIT) {
            load_stage(smbase, (c + 2) % NSTG, (c + 2) * BK, arow, seg, aH, aL, bH, predA);
            CPA_COMMIT();
        }
    }

#pragma unroll
    for (int i = 0; i < 2; i++)
#pragma unroll
        for (int rs = 0; rs < 2; rs++) {
            int m = mbase + wm * 32 + i * 16 + grp + rs * 8;
            if (m >= cnt) continue;
            size_t rowp = (size_t)(off + m) * H_DIM;
#pragma unroll
            for (int j = 0; j < 8; j++) {
                int col = n0 + wn * 64 + j * 8 + kq;
                *(float2*)(d_y + rowp + col) =
                    make_float2(acc[i][j][rs * 2], acc[i][j][rs * 2 + 1]);
            }
        }
}

// ---------------- 5. deterministic combine (float4 vectorized) ----------------
__global__ void combine_kernel(float4* __restrict__ out) {
    int idx = blockIdx.x * blockDim.x + threadIdx.x;   // < T*H/4
    int t = idx >> 9;           // H/4 = 512
    int c = (idx & 511) * 4;
    float w0 = d_wts[2 * t], w1 = d_wts[2 * t + 1];
    int s0 = d_slots[2 * t], s1 = d_slots[2 * t + 1];
    float4 a = *(const float4*)(d_y + (size_t)s0 * H_DIM + c);
    float4 b = *(const float4*)(d_y + (size_t)s1 * H_DIM + c);
    out[idx] = make_float4(w0 * a.x + w1 * b.x, w0 * a.y + w1 * b.y,
                           w0 * a.z + w1 * b.z, w0 * a.w + w1 * b.w);
}

// ---------------- launch ----------------
extern "C" void kernel_launch(void* const* d_in, const int* in_sizes, int n_in,
                              void* d_out, int out_size) {
    const float* x    = (const float*)d_in[0];
    const float* gw   = (const float*)d_in[1];
    const float* ws   = (const float*)d_in[2];
    const float* w2s  = (const float*)d_in[3];
    float* out = (float*)d_out;

    cudaFuncSetAttribute(gemm1_kernel, cudaFuncAttributeMaxDynamicSharedMemorySize, SMEM_BYTES);
    cudaFuncSetAttribute(gemm2_kernel, cudaFuncAttributeMaxDynamicSharedMemorySize, SMEM_BYTES);

    __half *xh, *xl, *wsh, *w2h;
    cudaGetSymbolAddress((void**)&xh,  d_xh);
    cudaGetSymbolAddress((void**)&xl,  d_xl);
    cudaGetSymbolAddress((void**)&wsh, d_wsh);
    cudaGetSymbolAddress((void**)&w2h, d_w2h);

    convert_hl_kernel<<<4096, 256>>>((const float4*)x, (uint4*)xh, (uint4*)xl);
    convert_hi_kernel<<<65536, 256>>>((const float4*)ws, (uint4*)wsh);
    convert_hi_kernel<<<32768, 256>>>((const float4*)w2s, (uint4*)w2h);

    gate_kernel<<<T_DIM, 128>>>(x, gw);
    count_kernel<<<E_NUM, 256>>>();
    offs_kernel<<<1, 1>>>();
    fill_kernel<<<E_NUM, 256>>>();

    dim3 g1(32, I_DIM / 64, E_NUM);    // (32, 32, 16)
    gemm1_kernel<<<g1, 256, SMEM_BYTES>>>();

    dim3 g2(32, H_DIM / 128, E_NUM);   // (32, 16, 16)
    gemm2_kernel<<<g2, 256, SMEM_BYTES>>>();

    combine_kernel<<<(T_DIM * H_DIM) / 4 / 256, 256>>>((float4*)out);
}

// round 12
// speedup vs baseline: 2.6835x; 1.4278x over previous
#include <cuda_runtime.h>
#include <cuda_fp16.h>
#include <cstdint>

#define T_DIM 4096
#define H_DIM 2048
#define I_DIM 2048
#define E_NUM 16

typedef unsigned long long ull;

// ---------------- static scratch (no allocations allowed) ----------------
__device__ int   d_ids[2 * T_DIM];
__device__ float d_wts[2 * T_DIM];
__device__ int   d_counts[E_NUM];
__device__ int   d_offs[E_NUM + 1];
__device__ int   d_tok[2 * T_DIM];
__device__ int   d_slots[2 * T_DIM];

// fp16 preconverted operands (hi-only everywhere; fp32 accumulate carries precision)
__device__ __half d_xh[(size_t)T_DIM * H_DIM];                // 16 MB
__device__ __half d_wsh[(size_t)E_NUM * 2 * I_DIM * H_DIM];   // 256 MB
__device__ __half d_w2h[(size_t)E_NUM * H_DIM * I_DIM];       // 128 MB
__device__ __half d_hh[(size_t)2 * T_DIM * I_DIM];            // 32 MB
__device__ float  d_y[(size_t)2 * T_DIM * H_DIM];             // 64 MB

// ---------------- GEMM config: BM=128, BN=128, BK=32, 8 warps (4M x 2N) ----------------
#define BK 32
#define STRIDE 40                        // halfs per smem row (conflict-free frags)
#define TILE_H (128 * STRIDE)            // 5120 halfs per 128x32 tile
#define STG_HALF (2 * TILE_H)            // AH + BH = 10240 halfs
#define STG_BYTES (STG_HALF * 2)         // 20480 B
#define NSTG 4
#define SMEM_BYTES (NSTG * STG_BYTES)    // 81920 B (x2 CTAs = 163840 < 228KB)

// mma.sync m16n8k16 fp16 inputs, fp32 accumulate (legacy tensor path on compute_103)
#define MMA16816(d, a, b0, b1)                                              \
    asm volatile(                                                           \
        "mma.sync.aligned.m16n8k16.row.col.f32.f16.f16.f32 "                \
        "{%0,%1,%2,%3}, {%4,%5,%6,%7}, {%8,%9}, {%0,%1,%2,%3};"             \
        : "+f"((d)[0]), "+f"((d)[1]), "+f"((d)[2]), "+f"((d)[3])            \
        : "r"((a)[0]), "r"((a)[1]), "r"((a)[2]), "r"((a)[3]),               \
          "r"(b0), "r"(b1))

// ldmatrix m8n8.x4 (sm_75+, valid on compute_103)
__device__ __forceinline__ void ldsm4(uint32_t* f, uint32_t a) {
    asm volatile("ldmatrix.sync.aligned.m8n8.x4.shared.b16 {%0,%1,%2,%3}, [%4];"
                 : "=r"(f[0]), "=r"(f[1]), "=r"(f[2]), "=r"(f[3]) : "r"(a));
}

__device__ __forceinline__ void cpa16(uint32_t dst, const void* src, int sz) {
    asm volatile("cp.async.cg.shared.global [%0], [%1], 16, %2;"
                 :: "r"(dst), "l"(src), "r"(sz));
}
#define CPA_COMMIT() asm volatile("cp.async.commit_group;" ::: "memory")
#define CPA_WAIT2()  asm volatile("cp.async.wait_group 2;" ::: "memory")
#define CPA_WAIT1()  asm volatile("cp.async.wait_group 1;" ::: "memory")
#define CPA_WAIT0()  asm volatile("cp.async.wait_group 0;" ::: "memory")

__device__ __forceinline__ uint32_t smem_u32(const void* p) {
    uint32_t a;
    asm("{ .reg .u64 t; cvta.to.shared.u64 t, %1; cvt.u32.u64 %0, t; }" : "=r"(a) : "l"(p));
    return a;
}

__device__ __forceinline__ uint32_t pack_h(float x, float y) {
    __half2 h = __floats2half2_rn(x, y);
    return *(uint32_t*)&h;
}

// ---------------- 0. convert fp32 -> fp16 (8 elems / thread) ----------------
__global__ void convert_hi_kernel(const float4* __restrict__ src, uint4* __restrict__ hi) {
    size_t i = (size_t)blockIdx.x * blockDim.x + threadIdx.x;
    float4 v0 = src[2 * i], v1 = src[2 * i + 1];
    hi[i] = make_uint4(pack_h(v0.x, v0.y), pack_h(v0.z, v0.w),
                       pack_h(v1.x, v1.y), pack_h(v1.z, v1.w));
}

// ---------------- 1. gating (float4 vectorized) ----------------
__global__ void gate_kernel(const float* __restrict__ x, const float* __restrict__ gw) {
    int t = blockIdx.x;
    int lane = threadIdx.x & 31;
    int w = threadIdx.x >> 5;
    const float* xr = x + (size_t)t * H_DIM;
    const float* g0 = gw + (size_t)(w * 4) * H_DIM;
    float acc0 = 0.f, acc1 = 0.f, acc2 = 0.f, acc3 = 0.f;
    for (int k = lane * 4; k < H_DIM; k += 128) {
        float4 xv = *(const float4*)(xr + k);
        float4 a0 = *(const float4*)(g0 + k);
        float4 a1 = *(const float4*)(g0 + H_DIM + k);
        float4 a2 = *(const float4*)(g0 + 2 * H_DIM + k);
        float4 a3 = *(const float4*)(g0 + 3 * H_DIM + k);
        acc0 += xv.x * a0.x + xv.y * a0.y + xv.z * a0.z + xv.w * a0.w;
        acc1 += xv.x * a1.x + xv.y * a1.y + xv.z * a1.z + xv.w * a1.w;
        acc2 += xv.x * a2.x + xv.y * a2.y + xv.z * a2.z + xv.w * a2.w;
        acc3 += xv.x * a3.x + xv.y * a3.y + xv.z * a3.z + xv.w * a3.w;
    }
    __shared__ float sl[16];
    float accs[4] = {acc0, acc1, acc2, acc3};
#pragma unroll
    for (int j = 0; j < 4; j++) {
        float v = accs[j];
#pragma unroll
        for (int o = 16; o; o >>= 1) v += __shfl_xor_sync(0xffffffff, v, o);
        if (lane == 0) sl[w * 4 + j] = v;
    }
    __syncthreads();
    if (threadIdx.x == 0) {
        float mx = sl[0];
#pragma unroll
        for (int i = 1; i < 16; i++) mx = fmaxf(mx, sl[i]);
        float ex[16];
#pragma unroll
        for (int i = 0; i < 16; i++) ex[i] = expf(sl[i] - mx);
        int b0 = 0;
#pragma unroll
        for (int i = 1; i < 16; i++) if (sl[i] > sl[b0]) b0 = i;
        int b1 = -1;
#pragma unroll
        for (int i = 0; i < 16; i++) {
            if (i == b0) continue;
            if (b1 < 0 || sl[i] > sl[b1]) b1 = i;
        }
        float s = ex[b0] + ex[b1];
        d_ids[2 * t] = b0;
        d_ids[2 * t + 1] = b1;
        d_wts[2 * t] = ex[b0] / s;
        d_wts[2 * t + 1] = ex[b1] / s;
    }
}

// ---------------- 2. routing (parallel segmented scans, deterministic) ----------------
__global__ void count_kernel() {
    int e = blockIdx.x;
    int w = threadIdx.x >> 5, lane = threadIdx.x & 31;
    __shared__ int wcnt[8];
    int cnt = 0;
#pragma unroll
    for (int i = 0; i < 16; i++) {
        int t = w * 512 + i * 32 + lane;
        bool p = (d_ids[2 * t] == e) || (d_ids[2 * t + 1] == e);
        cnt += __popc(__ballot_sync(0xffffffff, p));
    }
    if (lane == 0) wcnt[w] = cnt;
    __syncthreads();
    if (threadIdx.x == 0) {
        int s = 0;
#pragma unroll
        for (int i = 0; i < 8; i++) s += wcnt[i];
        d_counts[e] = s;
    }
}

__global__ void offs_kernel() {
    int s = 0;
    for (int e = 0; e < E_NUM; e++) { d_offs[e] = s; s += d_counts[e]; }
    d_offs[E_NUM] = s;
}

__global__ void fill_kernel() {
    int e = blockIdx.x;
    int w = threadIdx.x >> 5, lane = threadIdx.x & 31;
    __shared__ int wcnt[8], woff[8];
    int cnt = 0;
#pragma unroll
    for (int i = 0; i < 16; i++) {
        int t = w * 512 + i * 32 + lane;
        bool p = (d_ids[2 * t] == e) || (d_ids[2 * t + 1] == e);
        cnt += __popc(__ballot_sync(0xffffffff, p));
    }
    if (lane == 0) wcnt[w] = cnt;
    __syncthreads();
    if (threadIdx.x == 0) {
        int s = 0;
#pragma unroll
        for (int i = 0; i < 8; i++) { woff[i] = s; s += wcnt[i]; }
    }
    __syncthreads();
    int pos = d_offs[e] + woff[w];
#pragma unroll
    for (int i = 0; i < 16; i++) {
        int t = w * 512 + i * 32 + lane;
        int k = (d_ids[2 * t] == e) ? 0 : ((d_ids[2 * t + 1] == e) ? 1 : -1);
        unsigned b = __ballot_sync(0xffffffff, k >= 0);
        if (k >= 0) {
            int idx = pos + __popc(b & ((1u << lane) - 1u));
            d_tok[idx] = t;
            d_slots[2 * t + k] = idx;
        }
        pos += __popc(b);
    }
}

// =========== compute core: one BK=32 stage, warp tile 32x64, 1-term, ldmatrix ===========
__device__ __forceinline__ void mma_stage(uint32_t sb, uint32_t aoff, uint32_t boff,
                                          float acc[2][8][4]) {
#pragma unroll
    for (int ks = 0; ks < 2; ks++) {
        uint32_t ah[2][4];
#pragma unroll
        for (int i = 0; i < 2; i++)
            ldsm4(ah[i], sb + aoff + i * (16 * STRIDE * 2) + ks * 32);
#pragma unroll
        for (int jp = 0; jp < 4; jp++) {
            uint32_t bf[4];
            ldsm4(bf, sb + boff + jp * (16 * STRIDE * 2) + ks * 32);
#pragma unroll
            for (int i = 0; i < 2; i++) {
                MMA16816(acc[i][2 * jp],     ah[i], bf[0], bf[1]);
                MMA16816(acc[i][2 * jp + 1], ah[i], bf[2], bf[3]);
            }
        }
    }
}

// =========== loader: 4x cp.async 16B per thread (A hi, B hi) ===========
__device__ __forceinline__ void load_stage(uint32_t smbase, int s, int k0,
                                           int arow, int seg,
                                           const __half* aH, const __half* bH, int predA) {
    uint32_t sb = smbase + (uint32_t)s * STG_BYTES;
    uint32_t da = sb + (uint32_t)(arow * (STRIDE * 2) + seg * 32);
    cpa16(da,                  aH + k0,     predA);
    cpa16(da + 16,             aH + k0 + 8, predA);
    cpa16(da + TILE_H * 2,       bH + k0,     16);
    cpa16(da + TILE_H * 2 + 16,  bH + k0 + 8, 16);
}

// ldmatrix lane-offset helpers (byte offsets relative to stage base)
__device__ __forceinline__ uint32_t mk_aoff(int wm, int lane) {
    int row = wm * 32 + (lane & 7) + ((lane >> 3) & 1) * 8;
    int col8 = ((lane >> 4) & 1) * 8;
    return (uint32_t)((row * STRIDE + col8) * 2);
}
__device__ __forceinline__ uint32_t mk_boff(int wn, int lane) {
    int row = wn * 64 + (lane & 7) + (lane >> 4) * 8;
    int col8 = ((lane >> 3) & 1) * 8;
    return (uint32_t)((TILE_H + row * STRIDE + col8) * 2);
}

// ---------------- 3. GEMM1 + fused SiLU*U -> d_hh ----------------
// grid (32, I/64, E). B rows grouped: g=row>>5, icol = n0+(g>>1)*32+(row&31); g&1? up:gate
__global__ void __launch_bounds__(256, 2) gemm1_kernel() {
    int e = blockIdx.z;
    int cnt = d_counts[e];
    int mbase = blockIdx.x * 128;
    if (mbase >= cnt) return;
    int off = d_offs[e];
    int n0 = blockIdx.y * 64;

    extern __shared__ __align__(16) __half sm[];
    uint32_t smbase = smem_u32(sm);

    int tid = threadIdx.x;
    int lane = tid & 31, wid = tid >> 5;
    int wm = wid & 3, wn = wid >> 2;
    int grp = lane >> 2, kq = (lane & 3) * 2;

    int arow = tid >> 1;
    int seg = tid & 1;
    int mrow = mbase + arow;
    int predA = (mrow < cnt) ? 16 : 0;
    size_t atok = predA ? (size_t)d_tok[off + mrow] : 0;
    const __half* aH = d_xh + atok * H_DIM + seg * 16;
    int group = arow >> 5, rr = arow & 31;
    int icol = n0 + (group >> 1) * 32 + rr;
    size_t brow = (size_t)e * (2 * I_DIM) + ((group & 1) ? I_DIM + icol : icol);
    const __half* bH = d_wsh + brow * H_DIM + seg * 16;

    uint32_t aoff = mk_aoff(wm, lane), boff = mk_boff(wn, lane);

    float acc[2][8][4];
#pragma unroll
    for (int i = 0; i < 2; i++)
#pragma unroll
        for (int j = 0; j < 8; j++)
#pragma unroll
            for (int r = 0; r < 4; r++) acc[i][j][r] = 0.f;

    const int NIT = H_DIM / BK;
    load_stage(smbase, 0, 0, arow, seg, aH, bH, predA);
    CPA_COMMIT();
    load_stage(smbase, 1, BK, arow, seg, aH, bH, predA);
    CPA_COMMIT();
    load_stage(smbase, 2, 2 * BK, arow, seg, aH, bH, predA);
    CPA_COMMIT();
    for (int c = 0; c < NIT; c++) {
        if (c == NIT - 1)      { CPA_WAIT0(); }
        else if (c == NIT - 2) { CPA_WAIT1(); }
        else                   { CPA_WAIT2(); }
        __syncthreads();
        mma_stage(smbase + (uint32_t)(c % NSTG) * STG_BYTES, aoff, boff, acc);
        if (c + 3 < NIT) {
            load_stage(smbase, (c + 3) % NSTG, (c + 3) * BK, arow, seg, aH, bH, predA);
            CPA_COMMIT();
        }
    }

    // epilogue: silu(g)*u -> fp16  (warp wn: j=gate col, j+4=up col)
#pragma unroll
    for (int i = 0; i < 2; i++)
#pragma unroll
        for (int rs = 0; rs < 2; rs++) {
            int m = mbase + wm * 32 + i * 16 + grp + rs * 8;
            if (m >= cnt) continue;
            size_t rowp = (size_t)(off + m) * I_DIM;
#pragma unroll
            for (int j = 0; j < 4; j++) {
                int ic = n0 + wn * 32 + j * 8 + kq;
                float g0 = acc[i][j][rs * 2],     g1 = acc[i][j][rs * 2 + 1];
                float u0 = acc[i][j + 4][rs * 2], u1 = acc[i][j + 4][rs * 2 + 1];
                float h0 = u0 * g0 / (1.f + expf(-g0));
                float h1 = u1 * g1 / (1.f + expf(-g1));
                *(__half2*)(d_hh + rowp + ic) = __floats2half2_rn(h0, h1);
            }
        }
}

// ---------------- 4. GEMM2: y = h @ W2^T -> d_y ----------------
// grid (32, H/128, E). BM=128, BN=128, BK=32.
__global__ void __launch_bounds__(256, 2) gemm2_kernel() {
    int e = blockIdx.z;
    int cnt = d_counts[e];
    int mbase = blockIdx.x * 128;
    if (mbase >= cnt) return;
    int off = d_offs[e];
    int n0 = blockIdx.y * 128;

    extern __shared__ __align__(16) __half sm[];
    uint32_t smbase = smem_u32(sm);

    int tid = threadIdx.x;
    int lane = tid & 31, wid = tid >> 5;
    int wm = wid & 3, wn = wid >> 2;
    int grp = lane >> 2, kq = (lane & 3) * 2;

    int arow = tid >> 1;
    int seg = tid & 1;
    int mrow = mbase + arow;
    int predA = (mrow < cnt) ? 16 : 0;
    size_t aoff_g = predA ? (size_t)(off + mrow) : 0;
    const __half* aH = d_hh + aoff_g * I_DIM + seg * 16;
    const __half* bH = d_w2h + ((size_t)e * H_DIM + n0 + arow) * I_DIM + seg * 16;

    uint32_t aoff = mk_aoff(wm, lane), boff = mk_boff(wn, lane);

    float acc[2][8][4];
#pragma unroll
    for (int i = 0; i < 2; i++)
#pragma unroll
        for (int j = 0; j < 8; j++)
#pragma unroll
            for (int r = 0; r < 4; r++) acc[i][j][r] = 0.f;

    const int NIT = I_DIM / BK;
    load_stage(smbase, 0, 0, arow, seg, aH, bH, predA);
    CPA_COMMIT();
    load_stage(smbase, 1, BK, arow, seg, aH, bH, predA);
    CPA_COMMIT();
    load_stage(smbase, 2, 2 * BK, arow, seg, aH, bH, predA);
    CPA_COMMIT();
    for (int c = 0; c < NIT; c++) {
        if (c == NIT - 1)      { CPA_WAIT0(); }
        else if (c == NIT - 2) { CPA_WAIT1(); }
        else                   { CPA_WAIT2(); }
        __syncthreads();
        mma_stage(smbase + (uint32_t)(c % NSTG) * STG_BYTES, aoff, boff, acc);
        if (c + 3 < NIT) {
            load_stage(smbase, (c + 3) % NSTG, (c + 3) * BK, arow, seg, aH, bH, predA);
            CPA_COMMIT();
        }
    }

#pragma unroll
    for (int i = 0; i < 2; i++)
#pragma unroll
        for (int rs = 0; rs < 2; rs++) {
            int m = mbase + wm * 32 + i * 16 + grp + rs * 8;
            if (m >= cnt) continue;
            size_t rowp = (size_t)(off + m) * H_DIM;
#pragma unroll
            for (int j = 0; j < 8; j++) {
                int col = n0 + wn * 64 + j * 8 + kq;
                *(float2*)(d_y + rowp + col) =
                    make_float2(acc[i][j][rs * 2], acc[i][j][rs * 2 + 1]);
            }
        }
}

// ---------------- 5. deterministic combine (float4 vectorized) ----------------
__global__ void combine_kernel(float4* __restrict__ out) {
    int idx = blockIdx.x * blockDim.x + threadIdx.x;   // < T*H/4
    int t = idx >> 9;           // H/4 = 512
    int c = (idx & 511) * 4;
    float w0 = d_wts[2 * t], w1 = d_wts[2 * t + 1];
    int s0 = d_slots[2 * t], s1 = d_slots[2 * t + 1];
    float4 a = *(const float4*)(d_y + (size_t)s0 * H_DIM + c);
    float4 b = *(const float4*)(d_y + (size_t)s1 * H_DIM + c);
    out[idx] = make_float4(w0 * a.x + w1 * b.x, w0 * a.y + w1 * b.y,
                           w0 * a.z + w1 * b.z, w0 * a.w + w1 * b.w);
}

// ---------------- launch ----------------
extern "C" void kernel_launch(void* const* d_in, const int* in_sizes, int n_in,
                              void* d_out, int out_size) {
    const float* x    = (const float*)d_in[0];
    const float* gw   = (const float*)d_in[1];
    const float* ws   = (const float*)d_in[2];
    const float* w2s  = (const float*)d_in[3];
    float* out = (float*)d_out;

    cudaFuncSetAttribute(gemm1_kernel, cudaFuncAttributeMaxDynamicSharedMemorySize, SMEM_BYTES);
    cudaFuncSetAttribute(gemm2_kernel, cudaFuncAttributeMaxDynamicSharedMemorySize, SMEM_BYTES);

    __half *xh, *wsh, *w2h;
    cudaGetSymbolAddress((void**)&xh,  d_xh);
    cudaGetSymbolAddress((void**)&wsh, d_wsh);
    cudaGetSymbolAddress((void**)&w2h, d_w2h);

    convert_hi_kernel<<<4096, 256>>>((const float4*)x, (uint4*)xh);
    convert_hi_kernel<<<65536, 256>>>((const float4*)ws, (uint4*)wsh);
    convert_hi_kernel<<<32768, 256>>>((const float4*)w2s, (uint4*)w2h);

    gate_kernel<<<T_DIM, 128>>>(x, gw);
    count_kernel<<<E_NUM, 256>>>();
    offs_kernel<<<1, 1>>>();
    fill_kernel<<<E_NUM, 256>>>();

    dim3 g1(32, I_DIM / 64, E_NUM);    // (32, 32, 16)
    gemm1_kernel<<<g1, 256, SMEM_BYTES>>>();

    dim3 g2(32, H_DIM / 128, E_NUM);   // (32, 16, 16)
    gemm2_kernel<<<g2, 256, SMEM_BYTES>>>();

    combine_kernel<<<(T_DIM * H_DIM) / 4 / 256, 256>>>((float4*)out);
}